// round 8
// baseline (speedup 1.0000x reference)
#include <cuda_runtime.h>

// VAE forward, B = 4,000,000 rows, 2 rows/thread packed into f32x2 lanes,
// weights in __constant__ as duplicated (w,w) pairs -> LDCU uniform port.
//
// R6/R7 lessons combined: plain two-kernel launch (no PDL: it added 1.3us of
// launch overhead with nothing to overlap; no memcpy node: prep writes the
// constant bank directly) + uncapped registers (44 regs beats the 40-reg
// capped variant: 66.6us vs 68.3us kernel-side).
//
// Inputs: x[B,8], eps[B,4], w1[6,8], w21[4,6], w22[4,6], w3[6,4], w4[8,6]
// Output: concat(out[B,8], mu[B,4], logvar[B,4]) float32.

#define NT 256

typedef unsigned long long u64;

// Pair layout (u64 index): W1 [0,48) j*8+k | W21 [48,72) j*6+k | W22 [72,96)
//                          W3 [96,120) j*4+k | W4 [120,168) j*6+k
__constant__ ulonglong2 cw[84];

__device__ __forceinline__ u64 pk(float lo, float hi) {
    u64 d; asm("mov.b64 %0,{%1,%2};" : "=l"(d) : "f"(lo), "f"(hi)); return d;
}
__device__ __forceinline__ void upk(float& lo, float& hi, u64 v) {
    asm("mov.b64 {%0,%1},%2;" : "=f"(lo), "=f"(hi) : "l"(v));
}
__device__ __forceinline__ u64 fma2(u64 a, u64 b, u64 c) {
    u64 d; asm("fma.rn.f32x2 %0,%1,%2,%3;" : "=l"(d) : "l"(a), "l"(b), "l"(c)); return d;
}
__device__ __forceinline__ u64 mul2(u64 a, u64 b) {
    u64 d; asm("mul.rn.f32x2 %0,%1,%2;" : "=l"(d) : "l"(a), "l"(b)); return d;
}
__device__ __forceinline__ u64 elu2(u64 s) {
    float lo, hi; upk(lo, hi, s);
    lo = lo > 0.0f ? lo : (__expf(lo) - 1.0f);
    hi = hi > 0.0f ? hi : (__expf(hi) - 1.0f);
    return pk(lo, hi);
}

// Writes duplicated weight pairs straight into cw's backing store.
__global__ void prep_kernel(const float* __restrict__ w1,
                            const float* __restrict__ w21,
                            const float* __restrict__ w22,
                            const float* __restrict__ w3,
                            const float* __restrict__ w4,
                            u64* __restrict__ cw_backing)
{
    const int t = threadIdx.x;   // 168 threads
    float w;
    if (t < 48)       w = w1[t];
    else if (t < 72)  w = w21[t - 48];
    else if (t < 96)  w = w22[t - 72];
    else if (t < 120) w = w3[t - 96];
    else              w = w4[t - 120];
    cw_backing[t] = pk(w, w);
}

__global__ __launch_bounds__(NT)
void vae_kernel(const float4* __restrict__ x,
                const float4* __restrict__ eps,
                float4* __restrict__ out,
                float4* __restrict__ mu_out,
                float4* __restrict__ lv_out,
                int B)
{
    const int t  = threadIdx.x;
    const int i0 = blockIdx.x * (2 * NT) + t;
    const int i1 = i0 + NT;
    const bool v1 = i1 < B;
    if (i0 >= B) return;

    const float4 z4 = make_float4(0.f, 0.f, 0.f, 0.f);

    // ---- 6 front-batched LDG.128 ----
    const float4 xa0 = __ldcs(&x[2 * i0]);
    const float4 xb0 = __ldcs(&x[2 * i0 + 1]);
    const float4 e0  = __ldcs(&eps[i0]);
    const float4 xa1 = v1 ? __ldcs(&x[2 * i1])     : z4;
    const float4 xb1 = v1 ? __ldcs(&x[2 * i1 + 1]) : z4;
    const float4 e1  = v1 ? __ldcs(&eps[i1])       : z4;

    u64 X[8];
    X[0] = pk(xa0.x, xa1.x); X[1] = pk(xa0.y, xa1.y);
    X[2] = pk(xa0.z, xa1.z); X[3] = pk(xa0.w, xa1.w);
    X[4] = pk(xb0.x, xb1.x); X[5] = pk(xb0.y, xb1.y);
    X[6] = pk(xb0.z, xb1.z); X[7] = pk(xb0.w, xb1.w);
    u64 E[4];
    E[0] = pk(e0.x, e1.x); E[1] = pk(e0.y, e1.y);
    E[2] = pk(e0.z, e1.z); E[3] = pk(e0.w, e1.w);

    // ---- encoder: h1 = elu(x @ w1.T); weights via LDCU (uniform port) ----
    u64 h1[6];
#pragma unroll
    for (int j = 0; j < 6; j++) {
        const ulonglong2 p0 = cw[j * 4 + 0];
        const ulonglong2 p1 = cw[j * 4 + 1];
        const ulonglong2 p2 = cw[j * 4 + 2];
        const ulonglong2 p3 = cw[j * 4 + 3];
        u64 s = mul2(X[0], p0.x);
        s = fma2(X[1], p0.y, s);
        s = fma2(X[2], p1.x, s);
        s = fma2(X[3], p1.y, s);
        s = fma2(X[4], p2.x, s);
        s = fma2(X[5], p2.y, s);
        s = fma2(X[6], p3.x, s);
        s = fma2(X[7], p3.y, s);
        h1[j] = elu2(s);
    }

    // ---- mu / logvar ----
    u64 mu[4], lv[4];
#pragma unroll
    for (int j = 0; j < 4; j++) {
        const ulonglong2 m0 = cw[24 + j * 3 + 0];
        const ulonglong2 m1 = cw[24 + j * 3 + 1];
        const ulonglong2 m2 = cw[24 + j * 3 + 2];
        u64 sm = mul2(h1[0], m0.x);
        sm = fma2(h1[1], m0.y, sm);
        sm = fma2(h1[2], m1.x, sm);
        sm = fma2(h1[3], m1.y, sm);
        sm = fma2(h1[4], m2.x, sm);
        sm = fma2(h1[5], m2.y, sm);
        mu[j] = sm;
        const ulonglong2 l0 = cw[36 + j * 3 + 0];
        const ulonglong2 l1 = cw[36 + j * 3 + 1];
        const ulonglong2 l2 = cw[36 + j * 3 + 2];
        u64 sl = mul2(h1[0], l0.x);
        sl = fma2(h1[1], l0.y, sl);
        sl = fma2(h1[2], l1.x, sl);
        sl = fma2(h1[3], l1.y, sl);
        sl = fma2(h1[4], l2.x, sl);
        sl = fma2(h1[5], l2.y, sl);
        lv[j] = sl;
    }

    // ---- unpack mu/lv, store, reparameterize ----
    float m0a, m0b, m1a, m1b, m2a, m2b, m3a, m3b;
    upk(m0a, m0b, mu[0]); upk(m1a, m1b, mu[1]);
    upk(m2a, m2b, mu[2]); upk(m3a, m3b, mu[3]);
    float l0a, l0b, l1a, l1b, l2a, l2b, l3a, l3b;
    upk(l0a, l0b, lv[0]); upk(l1a, l1b, lv[1]);
    upk(l2a, l2b, lv[2]); upk(l3a, l3b, lv[3]);

    __stcs(&mu_out[i0], make_float4(m0a, m1a, m2a, m3a));
    __stcs(&lv_out[i0], make_float4(l0a, l1a, l2a, l3a));
    if (v1) {
        __stcs(&mu_out[i1], make_float4(m0b, m1b, m2b, m3b));
        __stcs(&lv_out[i1], make_float4(l0b, l1b, l2b, l3b));
    }

    u64 z[4];
    z[0] = fma2(E[0], pk(__expf(0.5f * l0a), __expf(0.5f * l0b)), mu[0]);
    z[1] = fma2(E[1], pk(__expf(0.5f * l1a), __expf(0.5f * l1b)), mu[1]);
    z[2] = fma2(E[2], pk(__expf(0.5f * l2a), __expf(0.5f * l2b)), mu[2]);
    z[3] = fma2(E[3], pk(__expf(0.5f * l3a), __expf(0.5f * l3b)), mu[3]);

    // ---- decoder: h3 = elu(z @ w3.T) ----
    u64 h3[6];
#pragma unroll
    for (int j = 0; j < 6; j++) {
        const ulonglong2 p0 = cw[48 + j * 2 + 0];
        const ulonglong2 p1 = cw[48 + j * 2 + 1];
        u64 s = mul2(z[0], p0.x);
        s = fma2(z[1], p0.y, s);
        s = fma2(z[2], p1.x, s);
        s = fma2(z[3], p1.y, s);
        h3[j] = elu2(s);
    }

    // ---- out = h3 @ w4.T ----
    float oa[8], ob[8];
#pragma unroll
    for (int j = 0; j < 8; j++) {
        const ulonglong2 p0 = cw[60 + j * 3 + 0];
        const ulonglong2 p1 = cw[60 + j * 3 + 1];
        const ulonglong2 p2 = cw[60 + j * 3 + 2];
        u64 s = mul2(h3[0], p0.x);
        s = fma2(h3[1], p0.y, s);
        s = fma2(h3[2], p1.x, s);
        s = fma2(h3[3], p1.y, s);
        s = fma2(h3[4], p2.x, s);
        s = fma2(h3[5], p2.y, s);
        upk(oa[j], ob[j], s);
    }

    __stcs(&out[2 * i0],     make_float4(oa[0], oa[1], oa[2], oa[3]));
    __stcs(&out[2 * i0 + 1], make_float4(oa[4], oa[5], oa[6], oa[7]));
    if (v1) {
        __stcs(&out[2 * i1],     make_float4(ob[0], ob[1], ob[2], ob[3]));
        __stcs(&out[2 * i1 + 1], make_float4(ob[4], ob[5], ob[6], ob[7]));
    }
}

extern "C" void kernel_launch(void* const* d_in, const int* in_sizes, int n_in,
                              void* d_out, int out_size)
{
    const float4* x   = (const float4*)d_in[0];
    const float4* eps = (const float4*)d_in[1];
    const float*  w1  = (const float*)d_in[2];
    const float*  w21 = (const float*)d_in[3];
    const float*  w22 = (const float*)d_in[4];
    const float*  w3  = (const float*)d_in[5];
    const float*  w4  = (const float*)d_in[6];

    const int B = in_sizes[0] / 8;

    float* outf = (float*)d_out;
    float4* out    = (float4*)outf;
    float4* mu_out = (float4*)(outf + (size_t)B * 8);
    float4* lv_out = (float4*)(outf + (size_t)B * 12);

    // prep kernel writes duplicated pairs straight into cw's backing store
    void* cw_ptr = nullptr;
    cudaGetSymbolAddress(&cw_ptr, cw);
    prep_kernel<<<1, 168>>>(w1, w21, w22, w3, w4, (u64*)cw_ptr);

    const int rows_per_block = 2 * NT;
    const int grid = (B + rows_per_block - 1) / rows_per_block;
    vae_kernel<<<grid, NT>>>(x, eps, out, mu_out, lv_out, B);
}

// round 9
// speedup vs baseline: 1.0098x; 1.0098x over previous
#include <cuda_runtime.h>

// VAE forward, B = 4,000,000 rows, 2 rows/thread packed into f32x2 lanes,
// weights in __constant__ as duplicated (w,w) pairs -> LDCU uniform port.
//
// R8 diagnosis: kernel stuck at 67.5us with NOTHING saturated (DRAM 73%,
// issue 58%, L1 47%, occ 52%) = latency-bound. R6's occupancy test was
// confounded by reg-cap codegen changes. Clean test this round: NT=128
// (44 regs unchanged -> 11 blocks/SM -> 44 warps = 68.75% theoretical occ,
// up from 40 warps/62.5%). Also fold 0.5 into the exp2 constant.
//
// Inputs: x[B,8], eps[B,4], w1[6,8], w21[4,6], w22[4,6], w3[6,4], w4[8,6]
// Output: concat(out[B,8], mu[B,4], logvar[B,4]) float32.

#define NT 128

typedef unsigned long long u64;

// Pair layout (u64 index): W1 [0,48) j*8+k | W21 [48,72) j*6+k | W22 [72,96)
//                          W3 [96,120) j*4+k | W4 [120,168) j*6+k
__constant__ ulonglong2 cw[84];

__device__ __forceinline__ u64 pk(float lo, float hi) {
    u64 d; asm("mov.b64 %0,{%1,%2};" : "=l"(d) : "f"(lo), "f"(hi)); return d;
}
__device__ __forceinline__ void upk(float& lo, float& hi, u64 v) {
    asm("mov.b64 {%0,%1},%2;" : "=f"(lo), "=f"(hi) : "l"(v));
}
__device__ __forceinline__ u64 fma2(u64 a, u64 b, u64 c) {
    u64 d; asm("fma.rn.f32x2 %0,%1,%2,%3;" : "=l"(d) : "l"(a), "l"(b), "l"(c)); return d;
}
__device__ __forceinline__ u64 mul2(u64 a, u64 b) {
    u64 d; asm("mul.rn.f32x2 %0,%1,%2;" : "=l"(d) : "l"(a), "l"(b)); return d;
}
__device__ __forceinline__ u64 elu2(u64 s) {
    float lo, hi; upk(lo, hi, s);
    lo = lo > 0.0f ? lo : (__expf(lo) - 1.0f);
    hi = hi > 0.0f ? hi : (__expf(hi) - 1.0f);
    return pk(lo, hi);
}
// exp(0.5*x) = 2^(x * 0.72134752)
__device__ __forceinline__ float exph(float v) {
    return exp2f(v * 0.72134752044448170368f);
}

// Writes duplicated weight pairs straight into cw's backing store.
__global__ void prep_kernel(const float* __restrict__ w1,
                            const float* __restrict__ w21,
                            const float* __restrict__ w22,
                            const float* __restrict__ w3,
                            const float* __restrict__ w4,
                            u64* __restrict__ cw_backing)
{
    const int t = threadIdx.x;   // 168 threads
    float w;
    if (t < 48)       w = w1[t];
    else if (t < 72)  w = w21[t - 48];
    else if (t < 96)  w = w22[t - 72];
    else if (t < 120) w = w3[t - 96];
    else              w = w4[t - 120];
    cw_backing[t] = pk(w, w);
}

__global__ __launch_bounds__(NT)
void vae_kernel(const float4* __restrict__ x,
                const float4* __restrict__ eps,
                float4* __restrict__ out,
                float4* __restrict__ mu_out,
                float4* __restrict__ lv_out,
                int B)
{
    const int t  = threadIdx.x;
    const int i0 = blockIdx.x * (2 * NT) + t;
    const int i1 = i0 + NT;
    const bool v1 = i1 < B;
    if (i0 >= B) return;

    const float4 z4 = make_float4(0.f, 0.f, 0.f, 0.f);

    // ---- 6 front-batched LDG.128 ----
    const float4 xa0 = __ldcs(&x[2 * i0]);
    const float4 xb0 = __ldcs(&x[2 * i0 + 1]);
    const float4 e0  = __ldcs(&eps[i0]);
    const float4 xa1 = v1 ? __ldcs(&x[2 * i1])     : z4;
    const float4 xb1 = v1 ? __ldcs(&x[2 * i1 + 1]) : z4;
    const float4 e1  = v1 ? __ldcs(&eps[i1])       : z4;

    u64 X[8];
    X[0] = pk(xa0.x, xa1.x); X[1] = pk(xa0.y, xa1.y);
    X[2] = pk(xa0.z, xa1.z); X[3] = pk(xa0.w, xa1.w);
    X[4] = pk(xb0.x, xb1.x); X[5] = pk(xb0.y, xb1.y);
    X[6] = pk(xb0.z, xb1.z); X[7] = pk(xb0.w, xb1.w);
    u64 E[4];
    E[0] = pk(e0.x, e1.x); E[1] = pk(e0.y, e1.y);
    E[2] = pk(e0.z, e1.z); E[3] = pk(e0.w, e1.w);

    // ---- encoder: h1 = elu(x @ w1.T); weights via LDCU (uniform port) ----
    u64 h1[6];
#pragma unroll
    for (int j = 0; j < 6; j++) {
        const ulonglong2 p0 = cw[j * 4 + 0];
        const ulonglong2 p1 = cw[j * 4 + 1];
        const ulonglong2 p2 = cw[j * 4 + 2];
        const ulonglong2 p3 = cw[j * 4 + 3];
        u64 s = mul2(X[0], p0.x);
        s = fma2(X[1], p0.y, s);
        s = fma2(X[2], p1.x, s);
        s = fma2(X[3], p1.y, s);
        s = fma2(X[4], p2.x, s);
        s = fma2(X[5], p2.y, s);
        s = fma2(X[6], p3.x, s);
        s = fma2(X[7], p3.y, s);
        h1[j] = elu2(s);
    }

    // ---- mu / logvar ----
    u64 mu[4], lv[4];
#pragma unroll
    for (int j = 0; j < 4; j++) {
        const ulonglong2 m0 = cw[24 + j * 3 + 0];
        const ulonglong2 m1 = cw[24 + j * 3 + 1];
        const ulonglong2 m2 = cw[24 + j * 3 + 2];
        u64 sm = mul2(h1[0], m0.x);
        sm = fma2(h1[1], m0.y, sm);
        sm = fma2(h1[2], m1.x, sm);
        sm = fma2(h1[3], m1.y, sm);
        sm = fma2(h1[4], m2.x, sm);
        sm = fma2(h1[5], m2.y, sm);
        mu[j] = sm;
        const ulonglong2 l0 = cw[36 + j * 3 + 0];
        const ulonglong2 l1 = cw[36 + j * 3 + 1];
        const ulonglong2 l2 = cw[36 + j * 3 + 2];
        u64 sl = mul2(h1[0], l0.x);
        sl = fma2(h1[1], l0.y, sl);
        sl = fma2(h1[2], l1.x, sl);
        sl = fma2(h1[3], l1.y, sl);
        sl = fma2(h1[4], l2.x, sl);
        sl = fma2(h1[5], l2.y, sl);
        lv[j] = sl;
    }

    // ---- unpack mu/lv, store, reparameterize ----
    float m0a, m0b, m1a, m1b, m2a, m2b, m3a, m3b;
    upk(m0a, m0b, mu[0]); upk(m1a, m1b, mu[1]);
    upk(m2a, m2b, mu[2]); upk(m3a, m3b, mu[3]);
    float l0a, l0b, l1a, l1b, l2a, l2b, l3a, l3b;
    upk(l0a, l0b, lv[0]); upk(l1a, l1b, lv[1]);
    upk(l2a, l2b, lv[2]); upk(l3a, l3b, lv[3]);

    __stcs(&mu_out[i0], make_float4(m0a, m1a, m2a, m3a));
    __stcs(&lv_out[i0], make_float4(l0a, l1a, l2a, l3a));
    if (v1) {
        __stcs(&mu_out[i1], make_float4(m0b, m1b, m2b, m3b));
        __stcs(&lv_out[i1], make_float4(l0b, l1b, l2b, l3b));
    }

    u64 z[4];
    z[0] = fma2(E[0], pk(exph(l0a), exph(l0b)), mu[0]);
    z[1] = fma2(E[1], pk(exph(l1a), exph(l1b)), mu[1]);
    z[2] = fma2(E[2], pk(exph(l2a), exph(l2b)), mu[2]);
    z[3] = fma2(E[3], pk(exph(l3a), exph(l3b)), mu[3]);

    // ---- decoder: h3 = elu(z @ w3.T) ----
    u64 h3[6];
#pragma unroll
    for (int j = 0; j < 6; j++) {
        const ulonglong2 p0 = cw[48 + j * 2 + 0];
        const ulonglong2 p1 = cw[48 + j * 2 + 1];
        u64 s = mul2(z[0], p0.x);
        s = fma2(z[1], p0.y, s);
        s = fma2(z[2], p1.x, s);
        s = fma2(z[3], p1.y, s);
        h3[j] = elu2(s);
    }

    // ---- out = h3 @ w4.T ----
    float oa[8], ob[8];
#pragma unroll
    for (int j = 0; j < 8; j++) {
        const ulonglong2 p0 = cw[60 + j * 3 + 0];
        const ulonglong2 p1 = cw[60 + j * 3 + 1];
        const ulonglong2 p2 = cw[60 + j * 3 + 2];
        u64 s = mul2(h3[0], p0.x);
        s = fma2(h3[1], p0.y, s);
        s = fma2(h3[2], p1.x, s);
        s = fma2(h3[3], p1.y, s);
        s = fma2(h3[4], p2.x, s);
        s = fma2(h3[5], p2.y, s);
        upk(oa[j], ob[j], s);
    }

    __stcs(&out[2 * i0],     make_float4(oa[0], oa[1], oa[2], oa[3]));
    __stcs(&out[2 * i0 + 1], make_float4(oa[4], oa[5], oa[6], oa[7]));
    if (v1) {
        __stcs(&out[2 * i1],     make_float4(ob[0], ob[1], ob[2], ob[3]));
        __stcs(&out[2 * i1 + 1], make_float4(ob[4], ob[5], ob[6], ob[7]));
    }
}

extern "C" void kernel_launch(void* const* d_in, const int* in_sizes, int n_in,
                              void* d_out, int out_size)
{
    const float4* x   = (const float4*)d_in[0];
    const float4* eps = (const float4*)d_in[1];
    const float*  w1  = (const float*)d_in[2];
    const float*  w21 = (const float*)d_in[3];
    const float*  w22 = (const float*)d_in[4];
    const float*  w3  = (const float*)d_in[5];
    const float*  w4  = (const float*)d_in[6];

    const int B = in_sizes[0] / 8;

    float* outf = (float*)d_out;
    float4* out    = (float4*)outf;
    float4* mu_out = (float4*)(outf + (size_t)B * 8);
    float4* lv_out = (float4*)(outf + (size_t)B * 12);

    // prep kernel writes duplicated pairs straight into cw's backing store
    void* cw_ptr = nullptr;
    cudaGetSymbolAddress(&cw_ptr, cw);
    prep_kernel<<<1, 168>>>(w1, w21, w22, w3, w4, (u64*)cw_ptr);

    const int rows_per_block = 2 * NT;
    const int grid = (B + rows_per_block - 1) / rows_per_block;
    vae_kernel<<<grid, NT>>>(x, eps, out, mu_out, lv_out, B);
}